// round 9
// baseline (speedup 1.0000x reference)
#include <cuda_runtime.h>

#define T_STEPS 500
#define NB 4096
#define RPC 32          // rows per CTA
#define NCTA (NB / RPC) // 128
#define NTHR 512

typedef unsigned long long ull;

// packed fp32x2 FMA (sm_103a FFMA2)
__device__ __forceinline__ ull ffma2(ull a, ull b, ull c) {
    ull d;
    asm("fma.rn.f32x2 %0, %1, %2, %3;" : "=l"(d) : "l"(a), "l"(b), "l"(c));
    return d;
}
__device__ __forceinline__ float pair_sum(ull p) {
    return __uint_as_float((unsigned)p) + __uint_as_float((unsigned)(p >> 32));
}
__device__ __forceinline__ ull packf2(float lo, float hi) {
    return (ull)__float_as_uint(lo) | ((ull)__float_as_uint(hi) << 32);
}

// SMEM: w1pk[2][16][128] ull, w2pk[2][32][65] ull (pad 65: il-lanes hit
// disjoint bank pairs), then floats hsm[2][32][128], pp[2][4][32][32],
// ys[32][32], b2s[64]
#define W1PK_U (2*16*128)          // 4096 ull
#define W2PK_U (2*32*65)           // 4160 ull
#define SMEM_BYTES ((W1PK_U + W2PK_U) * 8 + (8192 + 8192 + 1024 + 64) * 4)

__global__ __launch_bounds__(NTHR, 1)
void nsde5(const float* __restrict__ y0, const float* __restrict__ noise,
           const float* __restrict__ dw1, const float* __restrict__ db1,
           const float* __restrict__ dw2, const float* __restrict__ db2,
           const float* __restrict__ gw1, const float* __restrict__ gb1,
           const float* __restrict__ gw2, const float* __restrict__ gb2,
           float* __restrict__ out)
{
    extern __shared__ char smraw[];
    ull*   w1pk = (ull*)smraw;              // [m][kp][j]
    ull*   w2pk = w1pk + W1PK_U;            // [m][i][jp] stride 65
    float* hsm  = (float*)(w2pk + W2PK_U);  // [m][r][j]
    float* pp   = hsm + 8192;               // [m][q][r][i]
    float* ys   = pp  + 8192;               // [r][i]
    float* b2s  = ys  + 1024;               // [2][32]

    const int tid  = threadIdx.x;
    const int lane = tid & 31;
    const int wid  = tid >> 5;
    const int m    = wid >> 3;              // 0 drift, 1 diffusion
    const int base = blockIdx.x * RPC;

    // GEMM1 role: j-half (hj) + row-eighth (rq -> 8 rows)
    const int hj  = (wid >> 2) & 1;
    const int rb1 = (wid & 3) * 8;
    const int j0  = hj * 64 + lane;
    const int j1  = j0 + 32;

    // GEMM2 role: j-quarter (q) + row-half (rh); lane -> 2 outputs,
    // half-warp -> 8-row block
    const int q   = (wid >> 1) & 3;
    const int rh  = wid & 1;
    const int il  = lane & 15;
    const int rb2 = rh * 16 + (lane >> 4) * 8;

    // ---- stage W1 (k-packed) and W2 (j-packed) into SMEM ----
    for (int idx = tid; idx < W1PK_U; idx += NTHR) {
        int mm = idx >> 11, rest = idx & 2047;
        int kp = rest >> 7, j = rest & 127;
        const float* W = mm ? gw1 : dw1;
        w1pk[idx] = packf2(W[j * 32 + 2 * kp], W[j * 32 + 2 * kp + 1]);
    }
    for (int idx = tid; idx < 2 * 32 * 64; idx += NTHR) {
        int mm = idx >> 11, rest = idx & 2047;
        int i = rest >> 6, jp = rest & 63;
        const float* W = mm ? gw2 : dw2;
        w2pk[(mm * 32 + i) * 65 + jp] =
            packf2(W[i * 128 + 2 * jp], W[i * 128 + 2 * jp + 1]);
    }
    const float* B1 = m ? gb1 : db1;
    const float b1_0 = B1[j0], b1_1 = B1[j1];
    if (tid < 64) b2s[tid] = (tid < 32) ? db2[tid] : gb2[tid - 32];

    // ---- init ys + out[0] (2 elements per thread) ----
    #pragma unroll
    for (int vv = 0; vv < 2; vv++) {
        int v = tid + vv * NTHR;
        float val = y0[(size_t)base * 32 + v];
        ys[v] = val;
        out[(size_t)base * 32 + v] = val;
    }
    __syncthreads();

    const float dt   = 0.01f;
    const float sqdt = __fsqrt_rn(dt);
    const ull*   w1b  = w1pk + m * 2048;
    const ull*   w2b0 = w2pk + (m * 32 + il) * 65 + q * 16;
    const ull*   w2b1 = w2pk + (m * 32 + il + 16) * 65 + q * 16;
    const float* hq   = hsm + m * 4096 + q * 32;
    float*       ppb  = pp + (m * 4 + q) * 1024;

    for (int s = 0; s < T_STEPS; s++) {
        // prefetch step noise
        const size_t nbase = ((size_t)s * NB + base) * 32;
        float nn[2];
        #pragma unroll
        for (int vv = 0; vv < 2; vv++) nn[vv] = noise[nbase + tid + vv * NTHR];

        // ---- GEMM1: h[r][j0/j1] over 8 rows; 1 y-load -> 4 ffma2 ----
        ull acc0[8], acc1[8];
        const ull bi0 = (ull)__float_as_uint(b1_0);
        const ull bi1 = (ull)__float_as_uint(b1_1);
        #pragma unroll
        for (int r = 0; r < 8; r++) { acc0[r] = bi0; acc1[r] = bi1; }
        #pragma unroll
        for (int k4 = 0; k4 < 8; k4++) {
            ull w00 = w1b[(2*k4)   * 128 + j0];
            ull w01 = w1b[(2*k4+1) * 128 + j0];
            ull w10 = w1b[(2*k4)   * 128 + j1];
            ull w11 = w1b[(2*k4+1) * 128 + j1];
            #pragma unroll
            for (int r = 0; r < 8; r++) {
                double2 yv = *(const double2*)(ys + (rb1 + r) * 32 + k4 * 4);
                ull ylo = __double_as_longlong(yv.x);
                ull yhi = __double_as_longlong(yv.y);
                acc0[r] = ffma2(w00, ylo, acc0[r]);
                acc0[r] = ffma2(w01, yhi, acc0[r]);
                acc1[r] = ffma2(w10, ylo, acc1[r]);
                acc1[r] = ffma2(w11, yhi, acc1[r]);
            }
        }
        #pragma unroll
        for (int r = 0; r < 8; r++) {
            hsm[m * 4096 + (rb1 + r) * 128 + j0] = fmaxf(pair_sum(acc0[r]), 0.0f);
            hsm[m * 4096 + (rb1 + r) * 128 + j1] = fmaxf(pair_sum(acc1[r]), 0.0f);
        }
        __syncthreads();

        // ---- GEMM2: partial[r][il/il+16] over 8 rows; 1 h-load -> 4 ffma2 ----
        ull a0[8], a1[8];
        #pragma unroll
        for (int r = 0; r < 8; r++) { a0[r] = 0ull; a1[r] = 0ull; }
        #pragma unroll
        for (int j4 = 0; j4 < 8; j4++) {
            ull w20a = w2b0[2*j4];
            ull w20b = w2b0[2*j4+1];
            ull w21a = w2b1[2*j4];
            ull w21b = w2b1[2*j4+1];
            #pragma unroll
            for (int r = 0; r < 8; r++) {
                double2 hv = *(const double2*)(hq + (rb2 + r) * 128 + j4 * 4);
                ull hlo = __double_as_longlong(hv.x);
                ull hhi = __double_as_longlong(hv.y);
                a0[r] = ffma2(w20a, hlo, a0[r]);
                a0[r] = ffma2(w20b, hhi, a0[r]);
                a1[r] = ffma2(w21a, hlo, a1[r]);
                a1[r] = ffma2(w21b, hhi, a1[r]);
            }
        }
        #pragma unroll
        for (int r = 0; r < 8; r++) {
            ppb[(rb2 + r) * 32 + il]      = pair_sum(a0[r]);
            ppb[(rb2 + r) * 32 + il + 16] = pair_sum(a1[r]);
        }
        __syncthreads();

        // ---- reduce quarters + Euler–Maruyama (2 elements/thread) ----
        #pragma unroll
        for (int vv = 0; vv < 2; vv++) {
            int v = tid + vv * NTHR;
            int r = v >> 5, i = v & 31;
            const float* p = pp + r * 32 + i;
            float f = p[0] + p[1024] + p[2048] + p[3072] + b2s[i];
            const float* pg = p + 4096;
            float g = pg[0] + pg[1024] + pg[2048] + pg[3072] + b2s[32 + i];
            float z = fmaf(g, sqdt * nn[vv], fmaf(f, dt, ys[v]));
            out[((size_t)(s + 1) * NB + base) * 32 + v] = z;
            ys[v] = z;   // rewrites exactly the element it read
        }
        __syncthreads();
    }
}

extern "C" void kernel_launch(void* const* d_in, const int* in_sizes, int n_in,
                              void* d_out, int out_size)
{
    // metadata order: ts, y0, noise, drift_w1, drift_b1, drift_w2, drift_b2,
    //                 diff_w1, diff_b1, diff_w2, diff_b2
    const float* y0    = (const float*)d_in[1];
    const float* noise = (const float*)d_in[2];
    const float* dw1   = (const float*)d_in[3];
    const float* db1   = (const float*)d_in[4];
    const float* dw2   = (const float*)d_in[5];
    const float* db2   = (const float*)d_in[6];
    const float* gw1   = (const float*)d_in[7];
    const float* gb1   = (const float*)d_in[8];
    const float* gw2   = (const float*)d_in[9];
    const float* gb2   = (const float*)d_in[10];
    float* out = (float*)d_out;

    cudaFuncSetAttribute(nsde5,
                         cudaFuncAttributeMaxDynamicSharedMemorySize,
                         SMEM_BYTES);
    nsde5<<<NCTA, NTHR, SMEM_BYTES>>>(y0, noise, dw1, db1, dw2, db2,
                                      gw1, gb1, gw2, gb2, out);
}

// round 10
// speedup vs baseline: 1.2159x; 1.2159x over previous
#include <cuda_runtime.h>

#define T_STEPS 500
#define NB 4096
#define ROWS 28          // rows per CTA (with overlap; 148*28 >= 4096)
#define HR   14          // half rows
#define NCTA 148
#define NTHR 256

typedef unsigned long long ull;

// packed fp32x2 FMA (sm_103a FFMA2)
__device__ __forceinline__ ull ffma2(ull a, ull b, ull c) {
    ull d;
    asm("fma.rn.f32x2 %0, %1, %2, %3;" : "=l"(d) : "l"(a), "l"(b), "l"(c));
    return d;
}
__device__ __forceinline__ float pair_sum(ull p) {
    return __uint_as_float((unsigned)p) + __uint_as_float((unsigned)(p >> 32));
}
__device__ __forceinline__ ull packf2(float lo, float hi) {
    return (ull)__float_as_uint(lo) | ((ull)__float_as_uint(hi) << 32);
}

// SMEM: w1pk[2][16][128] ull, then floats hsm[2][28][128], pp[2][4][28][32],
//       ys[28][32], b2s[64]
#define W1PK_U (2*16*128)                 // 4096 ull = 32 KB
#define HSM_F  (2*ROWS*128)               // 7168
#define PP_F   (2*4*ROWS*32)              // 7168
#define YS_F   (ROWS*32)                  // 896
#define SMEM_BYTES (W1PK_U*8 + (HSM_F + PP_F + YS_F + 64)*4)

__global__ __launch_bounds__(NTHR, 1)
void nsde6(const float* __restrict__ y0, const float* __restrict__ noise,
           const float* __restrict__ dw1, const float* __restrict__ db1,
           const float* __restrict__ dw2, const float* __restrict__ db2,
           const float* __restrict__ gw1, const float* __restrict__ gb1,
           const float* __restrict__ gw2, const float* __restrict__ gb2,
           float* __restrict__ out)
{
    extern __shared__ char smraw[];
    ull*   w1pk = (ull*)smraw;              // [m][kp][j]
    float* hsm  = (float*)(w1pk + W1PK_U);  // [m][r][j]
    float* pp   = hsm + HSM_F;              // [m][q][r][i]
    float* ys   = pp  + PP_F;               // [r][i]
    float* b2s  = ys  + YS_F;               // [2][32]

    const int tid  = threadIdx.x;
    const int lane = tid & 31;
    const int wid  = tid >> 5;
    const int m    = wid >> 2;              // 0 drift, 1 diffusion
    // overlapping base: floor(bid*4068/147); coverage has no gaps, dup rows
    // are recomputed identically (deterministic duplicate writes)
    const int base = (int)(((long long)blockIdx.x * (NB - ROWS)) / (NCTA - 1));

    // GEMM1 role: j-half + r-half
    const int hj  = (wid >> 1) & 1;
    const int rb1 = (wid & 1) * HR;
    const int j0  = hj * 64 + lane;
    const int j1  = j0 + 32;

    // GEMM2 role: j-quarter; lane -> outputs il, il+16; half-warp -> r-half
    const int q   = wid & 3;
    const int il  = lane & 15;
    const int rb2 = (lane >> 4) * HR;

    // ---- stage W1 into SMEM as k-packed f32x2 ----
    for (int idx = tid; idx < W1PK_U; idx += NTHR) {
        int mm = idx >> 11, rest = idx & 2047;
        int kp = rest >> 7, j = rest & 127;
        const float* W = mm ? gw1 : dw1;
        w1pk[idx] = packf2(W[j * 32 + 2 * kp], W[j * 32 + 2 * kp + 1]);
    }
    // ---- W2 rows (i = il, il+16) for this quarter -> registers ----
    const float* W2 = m ? gw2 : dw2;
    ull w2p0[16], w2p1[16];
    #pragma unroll
    for (int t = 0; t < 8; t++) {
        double2 u0 = *(const double2*)(W2 + il * 128 + q * 32 + t * 4);
        w2p0[2*t]   = __double_as_longlong(u0.x);
        w2p0[2*t+1] = __double_as_longlong(u0.y);
        double2 u1 = *(const double2*)(W2 + (il + 16) * 128 + q * 32 + t * 4);
        w2p1[2*t]   = __double_as_longlong(u1.x);
        w2p1[2*t+1] = __double_as_longlong(u1.y);
    }
    const float* B1 = m ? gb1 : db1;
    const float b1_0 = B1[j0], b1_1 = B1[j1];
    if (tid < 64) b2s[tid] = (tid < 32) ? db2[tid] : gb2[tid - 32];

    // ---- init ys + out[0] (threads 0..223, one float4 each) ----
    if (tid < ROWS * 8) {
        int v4 = tid * 4;
        float4 val = *(const float4*)(y0 + (size_t)base * 32 + v4);
        *(float4*)(ys + v4) = val;
        *(float4*)(out + (size_t)base * 32 + v4) = val;
    }
    __syncthreads();

    const float dt   = 0.01f;
    const float sqdt = __fsqrt_rn(dt);
    const ull*   w1b = w1pk + m * 2048;
    const float* hq  = hsm + m * (ROWS * 128) + q * 32;
    float*       ppb = pp + (m * 4 + q) * (ROWS * 32);

    for (int s = 0; s < T_STEPS; s++) {
        // prefetch step noise (float4, threads 0..223)
        float4 nv;
        if (tid < ROWS * 8)
            nv = *(const float4*)(noise + ((size_t)s * NB + base) * 32 + tid * 4);

        // ---- GEMM1: h[r][j0/j1] over HR rows; 1 y-load -> 4 ffma2 ----
        ull acc0[HR], acc1[HR];
        const ull bi0 = (ull)__float_as_uint(b1_0);
        const ull bi1 = (ull)__float_as_uint(b1_1);
        #pragma unroll
        for (int r = 0; r < HR; r++) { acc0[r] = bi0; acc1[r] = bi1; }
        #pragma unroll
        for (int k4 = 0; k4 < 8; k4++) {
            ull w00 = w1b[(2*k4)   * 128 + j0];
            ull w01 = w1b[(2*k4+1) * 128 + j0];
            ull w10 = w1b[(2*k4)   * 128 + j1];
            ull w11 = w1b[(2*k4+1) * 128 + j1];
            #pragma unroll
            for (int r = 0; r < HR; r++) {
                double2 yv = *(const double2*)(ys + (rb1 + r) * 32 + k4 * 4);
                ull ylo = __double_as_longlong(yv.x);
                ull yhi = __double_as_longlong(yv.y);
                acc0[r] = ffma2(w00, ylo, acc0[r]);
                acc0[r] = ffma2(w01, yhi, acc0[r]);
                acc1[r] = ffma2(w10, ylo, acc1[r]);
                acc1[r] = ffma2(w11, yhi, acc1[r]);
            }
        }
        #pragma unroll
        for (int r = 0; r < HR; r++) {
            hsm[m * (ROWS*128) + (rb1 + r) * 128 + j0] = fmaxf(pair_sum(acc0[r]), 0.0f);
            hsm[m * (ROWS*128) + (rb1 + r) * 128 + j1] = fmaxf(pair_sum(acc1[r]), 0.0f);
        }
        __syncthreads();

        // ---- GEMM2: partial[r][il/il+16] over HR rows; 1 h-load -> 4 ffma2 ----
        ull a0[HR], a1[HR];
        #pragma unroll
        for (int r = 0; r < HR; r++) { a0[r] = 0ull; a1[r] = 0ull; }
        #pragma unroll
        for (int j4 = 0; j4 < 8; j4++) {
            #pragma unroll
            for (int r = 0; r < HR; r++) {
                double2 hv = *(const double2*)(hq + (rb2 + r) * 128 + j4 * 4);
                ull hlo = __double_as_longlong(hv.x);
                ull hhi = __double_as_longlong(hv.y);
                a0[r] = ffma2(w2p0[2*j4],   hlo, a0[r]);
                a0[r] = ffma2(w2p0[2*j4+1], hhi, a0[r]);
                a1[r] = ffma2(w2p1[2*j4],   hlo, a1[r]);
                a1[r] = ffma2(w2p1[2*j4+1], hhi, a1[r]);
            }
        }
        #pragma unroll
        for (int r = 0; r < HR; r++) {
            ppb[(rb2 + r) * 32 + il]      = pair_sum(a0[r]);
            ppb[(rb2 + r) * 32 + il + 16] = pair_sum(a1[r]);
        }
        __syncthreads();

        // ---- reduce quarters + Euler–Maruyama: threads 0..223, float4 each ----
        if (tid < ROWS * 8) {
            int v4 = tid * 4;
            const float* p = pp + v4;            // [r][i], i = v4&31 (mult of 4)
            float4 pa = *(const float4*)(p);
            float4 pb = *(const float4*)(p + ROWS*32);
            float4 pc = *(const float4*)(p + 2*ROWS*32);
            float4 pd = *(const float4*)(p + 3*ROWS*32);
            float4 bv = *(const float4*)(b2s + (v4 & 31));
            float fx = pa.x + pb.x + pc.x + pd.x + bv.x;
            float fy = pa.y + pb.y + pc.y + pd.y + bv.y;
            float fz = pa.z + pb.z + pc.z + pd.z + bv.z;
            float fw = pa.w + pb.w + pc.w + pd.w + bv.w;
            const float* pg = p + 4*ROWS*32;
            float4 ga = *(const float4*)(pg);
            float4 gb = *(const float4*)(pg + ROWS*32);
            float4 gc = *(const float4*)(pg + 2*ROWS*32);
            float4 gd = *(const float4*)(pg + 3*ROWS*32);
            float4 bg = *(const float4*)(b2s + 32 + (v4 & 31));
            float gx = ga.x + gb.x + gc.x + gd.x + bg.x;
            float gy = ga.y + gb.y + gc.y + gd.y + bg.y;
            float gz = ga.z + gb.z + gc.z + gd.z + bg.z;
            float gw = ga.w + gb.w + gc.w + gd.w + bg.w;
            float4 yv = *(const float4*)(ys + v4);
            float4 z;
            z.x = fmaf(gx, sqdt * nv.x, fmaf(fx, dt, yv.x));
            z.y = fmaf(gy, sqdt * nv.y, fmaf(fy, dt, yv.y));
            z.z = fmaf(gz, sqdt * nv.z, fmaf(fz, dt, yv.z));
            z.w = fmaf(gw, sqdt * nv.w, fmaf(fw, dt, yv.w));
            *(float4*)(out + ((size_t)(s + 1) * NB + base) * 32 + v4) = z;
            *(float4*)(ys + v4) = z;   // rewrites exactly what it read
        }
        __syncthreads();
    }
}

extern "C" void kernel_launch(void* const* d_in, const int* in_sizes, int n_in,
                              void* d_out, int out_size)
{
    // metadata order: ts, y0, noise, drift_w1, drift_b1, drift_w2, drift_b2,
    //                 diff_w1, diff_b1, diff_w2, diff_b2
    const float* y0    = (const float*)d_in[1];
    const float* noise = (const float*)d_in[2];
    const float* dw1   = (const float*)d_in[3];
    const float* db1   = (const float*)d_in[4];
    const float* dw2   = (const float*)d_in[5];
    const float* db2   = (const float*)d_in[6];
    const float* gw1   = (const float*)d_in[7];
    const float* gb1   = (const float*)d_in[8];
    const float* gw2   = (const float*)d_in[9];
    const float* gb2   = (const float*)d_in[10];
    float* out = (float*)d_out;

    cudaFuncSetAttribute(nsde6,
                         cudaFuncAttributeMaxDynamicSharedMemorySize,
                         SMEM_BYTES);
    nsde6<<<NCTA, NTHR, SMEM_BYTES>>>(y0, noise, dw1, db1, dw2, db2,
                                      gw1, gb1, gw2, gb2, out);
}